// round 1
// baseline (speedup 1.0000x reference)
#include <cuda_runtime.h>
#include <mma.h>

using namespace nvcuda;

// Problem constants (fixed shapes)
#define B_   2
#define S_   2048
#define D_   1024
#define H_   16
#define HD_  64
#define M_TOT (B_ * S_)   // 4096

// ---------------------------------------------------------------------------
// Scratch buffers (device globals; no allocation allowed in kernel_launch)
// ---------------------------------------------------------------------------
__device__ float g_q[B_ * H_ * S_ * HD_];    // [B,H,S,HD]
__device__ float g_k[B_ * H_ * S_ * HD_];
__device__ float g_v[B_ * H_ * S_ * HD_];
__device__ float g_att[B_ * S_ * D_];        // [B,S,D]

// ---------------------------------------------------------------------------
// TF32 WMMA GEMM:  out = A[M,K] @ W[K,N] + bias
//   qkv_mode == 1 : scatter output into [B,H,S,HD] head-major layout
//   qkv_mode == 0 : plain row-major [M,N]
// Block tile 128x64, K-step 32, 256 threads (8 warps, each 32x32 via 2x2 frags)
// ---------------------------------------------------------------------------
#define BM 128
#define BN 64
#define BK 32
#define ASTR (BK + 4)   // 36
#define BSTR (BN + 8)   // 72
#define CSTR (BN + 4)   // 68

__global__ void __launch_bounds__(256) gemm_tf32_kernel(
    const float* __restrict__ A, const float* __restrict__ W,
    const float* __restrict__ bias, float* __restrict__ out,
    int M, int N, int K, int qkv_mode)
{
    __shared__ float smem[BM * CSTR];  // 8704 floats; reused: As+Bs then Cs
    float* As = smem;                   // [BM][ASTR]
    float* Bs = smem + BM * ASTR;       // [BK][BSTR]

    const int bm = blockIdx.y * BM;
    const int bn = blockIdx.x * BN;
    const int tid = threadIdx.x;
    const int warp = tid >> 5;
    const int wm = (warp >> 1) * 32;   // 0,32,64,96
    const int wn = (warp & 1) * 32;    // 0,32

    wmma::fragment<wmma::accumulator, 16, 16, 8, float> acc[2][2];
#pragma unroll
    for (int i = 0; i < 2; i++)
#pragma unroll
        for (int j = 0; j < 2; j++)
            wmma::fill_fragment(acc[i][j], 0.0f);

    for (int k0 = 0; k0 < K; k0 += BK) {
        // Load A tile 128x32 (tf32-converted)
#pragma unroll
        for (int p = 0; p < 4; p++) {
            int r = p * 32 + (tid >> 3);
            int c = (tid & 7) * 4;
            float4 v = *(const float4*)(A + (size_t)(bm + r) * K + k0 + c);
            float* dst = As + r * ASTR + c;
            dst[0] = wmma::__float_to_tf32(v.x);
            dst[1] = wmma::__float_to_tf32(v.y);
            dst[2] = wmma::__float_to_tf32(v.z);
            dst[3] = wmma::__float_to_tf32(v.w);
        }
        // Load B tile 32x64 (tf32-converted)
#pragma unroll
        for (int p = 0; p < 2; p++) {
            int r = p * 16 + (tid >> 4);
            int c = (tid & 15) * 4;
            float4 v = *(const float4*)(W + (size_t)(k0 + r) * N + bn + c);
            float* dst = Bs + r * BSTR + c;
            dst[0] = wmma::__float_to_tf32(v.x);
            dst[1] = wmma::__float_to_tf32(v.y);
            dst[2] = wmma::__float_to_tf32(v.z);
            dst[3] = wmma::__float_to_tf32(v.w);
        }
        __syncthreads();

#pragma unroll
        for (int kk = 0; kk < BK; kk += 8) {
            wmma::fragment<wmma::matrix_a, 16, 16, 8, wmma::precision::tf32, wmma::row_major> fa[2];
            wmma::fragment<wmma::matrix_b, 16, 16, 8, wmma::precision::tf32, wmma::row_major> fb[2];
#pragma unroll
            for (int i = 0; i < 2; i++)
                wmma::load_matrix_sync(fa[i], As + (wm + i * 16) * ASTR + kk, ASTR);
#pragma unroll
            for (int j = 0; j < 2; j++)
                wmma::load_matrix_sync(fb[j], Bs + kk * BSTR + wn + j * 16, BSTR);
#pragma unroll
            for (int i = 0; i < 2; i++)
#pragma unroll
                for (int j = 0; j < 2; j++)
                    wmma::mma_sync(acc[i][j], fa[i], fb[j], acc[i][j]);
        }
        __syncthreads();
    }

    // Epilogue: stage C in shared, then add bias + write with layout remap
    float* Cs = smem;
#pragma unroll
    for (int i = 0; i < 2; i++)
#pragma unroll
        for (int j = 0; j < 2; j++)
            wmma::store_matrix_sync(Cs + (wm + i * 16) * CSTR + wn + j * 16,
                                    acc[i][j], CSTR, wmma::mem_row_major);
    __syncthreads();

#pragma unroll
    for (int p = 0; p < 8; p++) {
        int r = p * 16 + (tid >> 4);
        int c = (tid & 15) * 4;
        float4 v = *(float4*)(Cs + r * CSTR + c);
        int n = bn + c;
        float4 bv = *(const float4*)(bias + n);
        v.x += bv.x; v.y += bv.y; v.z += bv.z; v.w += bv.w;
        int m = bm + r;
        if (qkv_mode) {
            int b = m / S_, s = m % S_;
            int h = n / HD_, d = n % HD_;
            *(float4*)(out + ((size_t)((b * H_ + h) * S_ + s)) * HD_ + d) = v;
        } else {
            *(float4*)(out + (size_t)m * N + n) = v;
        }
    }
}

// ---------------------------------------------------------------------------
// Flash attention: per (b*h, q-tile) CTA, online softmax, TF32 WMMA for both
// Q@K^T and P@V. Q tile 64, KV tile 64, 256 threads (8 warps).
// ---------------------------------------------------------------------------
#define AQ  64
#define AKV 64
#define AST 72   // shared stride (multiple of 8 floats)

__global__ void __launch_bounds__(256) attn_kernel(
    const float* __restrict__ Qb, const float* __restrict__ Kb,
    const float* __restrict__ Vb, float* __restrict__ Ob)
{
    extern __shared__ float sm[];
    float* Qs  = sm;                    // [AQ][AST]  tf32
    float* Ks  = Qs + AQ * AST;         // [AKV][AST] tf32
    float* Vs  = Ks + AKV * AST;        // [AKV][AST] tf32
    float* Ss  = Vs + AKV * AST;        // [AQ][AST]  scores, then P (tf32)
    float* PVs = Ss + AQ * AST;         // [AQ][AST]  P@V staging

    const int bh  = blockIdx.y;         // 0..31  (b*H + h)
    const int qt  = blockIdx.x;         // 0..31
    const int tid = threadIdx.x;
    const int warp = tid >> 5;
    const float scale = 0.125f;         // 1/sqrt(64)

    // Load Q tile (tf32)
    const float* Qp = Qb + ((size_t)bh * S_ + qt * AQ) * HD_;
#pragma unroll
    for (int p = 0; p < 4; p++) {
        int r = p * 16 + (tid >> 4);
        int c = (tid & 15) * 4;
        float4 v = *(const float4*)(Qp + (size_t)r * HD_ + c);
        float* dst = Qs + r * AST + c;
        dst[0] = wmma::__float_to_tf32(v.x);
        dst[1] = wmma::__float_to_tf32(v.y);
        dst[2] = wmma::__float_to_tf32(v.z);
        dst[3] = wmma::__float_to_tf32(v.w);
    }

    const int row  = tid >> 2;          // 0..63 softmax row owned
    const int cseg = (tid & 3) * 16;    // 16-col segment within row
    float Oacc[16];
#pragma unroll
    for (int i = 0; i < 16; i++) Oacc[i] = 0.0f;
    float m_run = -1e30f, l_run = 0.0f;

    const int wm2 = (warp >> 2) * 32;   // 0 or 32
    const int wn2 = (warp & 3) * 16;    // 0,16,32,48

    __syncthreads();

    for (int kt = 0; kt < S_ / AKV; kt++) {
        // Load K and V tiles (tf32)
        const float* Kp = Kb + ((size_t)bh * S_ + kt * AKV) * HD_;
        const float* Vp = Vb + ((size_t)bh * S_ + kt * AKV) * HD_;
#pragma unroll
        for (int p = 0; p < 4; p++) {
            int r = p * 16 + (tid >> 4);
            int c = (tid & 15) * 4;
            float4 kv = *(const float4*)(Kp + (size_t)r * HD_ + c);
            float* kd = Ks + r * AST + c;
            kd[0] = wmma::__float_to_tf32(kv.x);
            kd[1] = wmma::__float_to_tf32(kv.y);
            kd[2] = wmma::__float_to_tf32(kv.z);
            kd[3] = wmma::__float_to_tf32(kv.w);
            float4 vv = *(const float4*)(Vp + (size_t)r * HD_ + c);
            float* vd = Vs + r * AST + c;
            vd[0] = wmma::__float_to_tf32(vv.x);
            vd[1] = wmma::__float_to_tf32(vv.y);
            vd[2] = wmma::__float_to_tf32(vv.z);
            vd[3] = wmma::__float_to_tf32(vv.w);
        }
        __syncthreads();

        // S = scale * Q @ K^T   (B = K tile used as col-major = K^T)
        {
            wmma::fragment<wmma::accumulator, 16, 16, 8, float> sacc[2];
#pragma unroll
            for (int i = 0; i < 2; i++) wmma::fill_fragment(sacc[i], 0.0f);
#pragma unroll
            for (int kk = 0; kk < HD_; kk += 8) {
                wmma::fragment<wmma::matrix_a, 16, 16, 8, wmma::precision::tf32, wmma::row_major> fa[2];
                wmma::fragment<wmma::matrix_b, 16, 16, 8, wmma::precision::tf32, wmma::col_major> fb;
#pragma unroll
                for (int i = 0; i < 2; i++)
                    wmma::load_matrix_sync(fa[i], Qs + (wm2 + i * 16) * AST + kk, AST);
                wmma::load_matrix_sync(fb, Ks + wn2 * AST + kk, AST);
#pragma unroll
                for (int i = 0; i < 2; i++)
                    wmma::mma_sync(sacc[i], fa[i], fb, sacc[i]);
            }
#pragma unroll
            for (int i = 0; i < 2; i++) {
#pragma unroll
                for (int e = 0; e < sacc[i].num_elements; e++) sacc[i].x[e] *= scale;
                wmma::store_matrix_sync(Ss + (wm2 + i * 16) * AST + wn2, sacc[i],
                                        AST, wmma::mem_row_major);
            }
        }
        __syncthreads();

        // Online softmax update (4 threads per row, 16 cols each)
        {
            float* srow = Ss + row * AST + cseg;
            float vloc[16];
            float mx = -1e30f;
#pragma unroll
            for (int i = 0; i < 16; i++) { vloc[i] = srow[i]; mx = fmaxf(mx, vloc[i]); }
            mx = fmaxf(mx, __shfl_xor_sync(0xffffffffu, mx, 1));
            mx = fmaxf(mx, __shfl_xor_sync(0xffffffffu, mx, 2));
            float m_new = fmaxf(m_run, mx);
            float alpha = __expf(m_run - m_new);
            float s_loc = 0.0f;
#pragma unroll
            for (int i = 0; i < 16; i++) {
                float pz = __expf(vloc[i] - m_new);
                s_loc += pz;
                srow[i] = wmma::__float_to_tf32(pz);
            }
            s_loc += __shfl_xor_sync(0xffffffffu, s_loc, 1);
            s_loc += __shfl_xor_sync(0xffffffffu, s_loc, 2);
            l_run = l_run * alpha + s_loc;
            m_run = m_new;
#pragma unroll
            for (int i = 0; i < 16; i++) Oacc[i] *= alpha;
        }
        __syncthreads();

        // PV = P @ V
        {
            wmma::fragment<wmma::accumulator, 16, 16, 8, float> pv[2];
#pragma unroll
            for (int i = 0; i < 2; i++) wmma::fill_fragment(pv[i], 0.0f);
#pragma unroll
            for (int kk = 0; kk < AKV; kk += 8) {
                wmma::fragment<wmma::matrix_a, 16, 16, 8, wmma::precision::tf32, wmma::row_major> fa[2];
                wmma::fragment<wmma::matrix_b, 16, 16, 8, wmma::precision::tf32, wmma::row_major> fb;
#pragma unroll
                for (int i = 0; i < 2; i++)
                    wmma::load_matrix_sync(fa[i], Ss + (wm2 + i * 16) * AST + kk, AST);
                wmma::load_matrix_sync(fb, Vs + kk * AST + wn2, AST);
#pragma unroll
                for (int i = 0; i < 2; i++)
                    wmma::mma_sync(pv[i], fa[i], fb, pv[i]);
            }
#pragma unroll
            for (int i = 0; i < 2; i++)
                wmma::store_matrix_sync(PVs + (wm2 + i * 16) * AST + wn2, pv[i],
                                        AST, wmma::mem_row_major);
        }
        __syncthreads();

#pragma unroll
        for (int i = 0; i < 16; i++) Oacc[i] += PVs[row * AST + cseg + i];
        __syncthreads();
    }

    // Normalize and write to [B,S,D] (h interleaved back)
    float inv_l = 1.0f / l_run;
    int b = bh / H_, h = bh % H_;
    float* op = Ob + ((size_t)(b * S_ + qt * AQ + row)) * D_ + h * HD_ + cseg;
#pragma unroll
    for (int p = 0; p < 4; p++) {
        float4 v;
        v.x = Oacc[p * 4 + 0] * inv_l;
        v.y = Oacc[p * 4 + 1] * inv_l;
        v.z = Oacc[p * 4 + 2] * inv_l;
        v.w = Oacc[p * 4 + 3] * inv_l;
        *(float4*)(op + p * 4) = v;
    }
}

// ---------------------------------------------------------------------------
// Launch
// ---------------------------------------------------------------------------
extern "C" void kernel_launch(void* const* d_in, const int* in_sizes, int n_in,
                              void* d_out, int out_size)
{
    (void)in_sizes; (void)n_in; (void)out_size;
    const float* x  = (const float*)d_in[0];
    const float* Wq = (const float*)d_in[1];
    const float* bq = (const float*)d_in[2];
    const float* Wk = (const float*)d_in[3];
    const float* bk = (const float*)d_in[4];
    const float* Wv = (const float*)d_in[5];
    const float* bv = (const float*)d_in[6];
    const float* Wo = (const float*)d_in[7];
    const float* bo = (const float*)d_in[8];
    float* out = (float*)d_out;

    void *pq, *pk, *pv, *patt;
    cudaGetSymbolAddress(&pq, g_q);
    cudaGetSymbolAddress(&pk, g_k);
    cudaGetSymbolAddress(&pv, g_v);
    cudaGetSymbolAddress(&patt, g_att);
    float* qb = (float*)pq;
    float* kb = (float*)pk;
    float* vb = (float*)pv;
    float* ab = (float*)patt;

    const int ATT_SMEM = 5 * AQ * AST * (int)sizeof(float);  // 92160 B
    cudaFuncSetAttribute(attn_kernel, cudaFuncAttributeMaxDynamicSharedMemorySize, ATT_SMEM);

    dim3 ggrid(D_ / BN, M_TOT / BM);   // (16, 32)
    gemm_tf32_kernel<<<ggrid, 256>>>(x, Wq, bq, qb, M_TOT, D_, D_, 1);
    gemm_tf32_kernel<<<ggrid, 256>>>(x, Wk, bk, kb, M_TOT, D_, D_, 1);
    gemm_tf32_kernel<<<ggrid, 256>>>(x, Wv, bv, vb, M_TOT, D_, D_, 1);

    dim3 agrid(S_ / AQ, B_ * H_);      // (32, 32)
    attn_kernel<<<agrid, 256, ATT_SMEM>>>(qb, kb, vb, ab);

    gemm_tf32_kernel<<<ggrid, 256>>>(ab, Wo, bo, out, M_TOT, D_, D_, 0);
}

// round 2
// speedup vs baseline: 1.4942x; 1.4942x over previous
#include <cuda_runtime.h>
#include <mma.h>

using namespace nvcuda;

// Problem constants (fixed shapes)
#define B_   2
#define S_   2048
#define D_   1024
#define H_   16
#define HD_  64
#define M_TOT (B_ * S_)   // 4096

// ---------------------------------------------------------------------------
// Scratch buffers
// ---------------------------------------------------------------------------
__device__ float g_q[B_ * H_ * S_ * HD_];    // [B,H,S,HD]
__device__ float g_k[B_ * H_ * S_ * HD_];
__device__ float g_v[B_ * H_ * S_ * HD_];
__device__ float g_att[B_ * S_ * D_];        // [B,S,D]

// ---------------------------------------------------------------------------
// Helpers
// ---------------------------------------------------------------------------
__device__ __forceinline__ unsigned f2tf(float x) {
    unsigned u;
    asm("cvt.rna.tf32.f32 %0, %1;" : "=r"(u) : "f"(x));
    return u;
}

__device__ __forceinline__ void mma_tf32(float* d, const unsigned* a,
                                         unsigned b0, unsigned b1) {
    asm volatile(
        "mma.sync.aligned.m16n8k8.row.col.f32.tf32.tf32.f32 "
        "{%0,%1,%2,%3}, {%4,%5,%6,%7}, {%8,%9}, {%0,%1,%2,%3};"
        : "+f"(d[0]), "+f"(d[1]), "+f"(d[2]), "+f"(d[3])
        : "r"(a[0]), "r"(a[1]), "r"(a[2]), "r"(a[3]), "r"(b0), "r"(b1));
}

// ---------------------------------------------------------------------------
// TF32 WMMA GEMM (unchanged from R1):  out = A[M,K] @ W[K,N] + bias
// ---------------------------------------------------------------------------
#define BM 128
#define BN 64
#define BK 32
#define ASTR (BK + 4)
#define BSTR (BN + 8)
#define CSTR (BN + 4)

__global__ void __launch_bounds__(256) gemm_tf32_kernel(
    const float* __restrict__ A, const float* __restrict__ W,
    const float* __restrict__ bias, float* __restrict__ out,
    int M, int N, int K, int qkv_mode)
{
    __shared__ float smem[BM * CSTR];
    float* As = smem;
    float* Bs = smem + BM * ASTR;

    const int bm = blockIdx.y * BM;
    const int bn = blockIdx.x * BN;
    const int tid = threadIdx.x;
    const int warp = tid >> 5;
    const int wm = (warp >> 1) * 32;
    const int wn = (warp & 1) * 32;

    wmma::fragment<wmma::accumulator, 16, 16, 8, float> acc[2][2];
#pragma unroll
    for (int i = 0; i < 2; i++)
#pragma unroll
        for (int j = 0; j < 2; j++)
            wmma::fill_fragment(acc[i][j], 0.0f);

    for (int k0 = 0; k0 < K; k0 += BK) {
#pragma unroll
        for (int p = 0; p < 4; p++) {
            int r = p * 32 + (tid >> 3);
            int c = (tid & 7) * 4;
            float4 v = *(const float4*)(A + (size_t)(bm + r) * K + k0 + c);
            float* dst = As + r * ASTR + c;
            dst[0] = wmma::__float_to_tf32(v.x);
            dst[1] = wmma::__float_to_tf32(v.y);
            dst[2] = wmma::__float_to_tf32(v.z);
            dst[3] = wmma::__float_to_tf32(v.w);
        }
#pragma unroll
        for (int p = 0; p < 2; p++) {
            int r = p * 16 + (tid >> 4);
            int c = (tid & 15) * 4;
            float4 v = *(const float4*)(W + (size_t)(k0 + r) * N + bn + c);
            float* dst = Bs + r * BSTR + c;
            dst[0] = wmma::__float_to_tf32(v.x);
            dst[1] = wmma::__float_to_tf32(v.y);
            dst[2] = wmma::__float_to_tf32(v.z);
            dst[3] = wmma::__float_to_tf32(v.w);
        }
        __syncthreads();

#pragma unroll
        for (int kk = 0; kk < BK; kk += 8) {
            wmma::fragment<wmma::matrix_a, 16, 16, 8, wmma::precision::tf32, wmma::row_major> fa[2];
            wmma::fragment<wmma::matrix_b, 16, 16, 8, wmma::precision::tf32, wmma::row_major> fb[2];
#pragma unroll
            for (int i = 0; i < 2; i++)
                wmma::load_matrix_sync(fa[i], As + (wm + i * 16) * ASTR + kk, ASTR);
#pragma unroll
            for (int j = 0; j < 2; j++)
                wmma::load_matrix_sync(fb[j], Bs + kk * BSTR + wn + j * 16, BSTR);
#pragma unroll
            for (int i = 0; i < 2; i++)
#pragma unroll
                for (int j = 0; j < 2; j++)
                    wmma::mma_sync(acc[i][j], fa[i], fb[j], acc[i][j]);
        }
        __syncthreads();
    }

    float* Cs = smem;
#pragma unroll
    for (int i = 0; i < 2; i++)
#pragma unroll
        for (int j = 0; j < 2; j++)
            wmma::store_matrix_sync(Cs + (wm + i * 16) * CSTR + wn + j * 16,
                                    acc[i][j], CSTR, wmma::mem_row_major);
    __syncthreads();

#pragma unroll
    for (int p = 0; p < 8; p++) {
        int r = p * 16 + (tid >> 4);
        int c = (tid & 15) * 4;
        float4 v = *(float4*)(Cs + r * CSTR + c);
        int n = bn + c;
        float4 bv = *(const float4*)(bias + n);
        v.x += bv.x; v.y += bv.y; v.z += bv.z; v.w += bv.w;
        int m = bm + r;
        if (qkv_mode) {
            int b = m / S_, s = m % S_;
            int h = n / HD_, d = n % HD_;
            *(float4*)(out + ((size_t)((b * H_ + h) * S_ + s)) * HD_ + d) = v;
        } else {
            *(float4*)(out + (size_t)m * N + n) = v;
        }
    }
}

// ---------------------------------------------------------------------------
// Flash attention v2: register-resident S/P/O via raw mma.m16n8k8 TF32.
// 4 warps, Q tile 64 (16 rows/warp), KV tile 64. smem = K,V tiles only.
// ---------------------------------------------------------------------------
#define AQ  64
#define AKV 64
#define AST 68   // 64+4 floats; 68%32=4 -> conflict-free frag loads

__global__ void __launch_bounds__(128) attn_kernel(
    const float* __restrict__ Qb, const float* __restrict__ Kb,
    const float* __restrict__ Vb, float* __restrict__ Ob)
{
    __shared__ float Ks[AKV * AST];
    __shared__ float Vs[AKV * AST];

    const int bh   = blockIdx.y;     // b*H + h
    const int qt   = blockIdx.x;
    const int tid  = threadIdx.x;
    const int warp = tid >> 5;
    const int lane = tid & 31;
    const int g    = lane >> 2;      // group id 0..7
    const int tig  = lane & 3;       // thread-in-group 0..3

    // ---- Load Q fragments once, with softmax scale folded in ----
    const int qrow0 = qt * AQ + warp * 16;
    const float* Qp = Qb + ((size_t)bh * S_ + qrow0) * HD_;
    unsigned qa[8][4];
#pragma unroll
    for (int kc = 0; kc < 8; kc++) {
        int c0 = kc * 8 + tig;
        qa[kc][0] = f2tf(Qp[(size_t)g * HD_ + c0] * 0.125f);
        qa[kc][1] = f2tf(Qp[(size_t)(g + 8) * HD_ + c0] * 0.125f);
        qa[kc][2] = f2tf(Qp[(size_t)g * HD_ + c0 + 4] * 0.125f);
        qa[kc][3] = f2tf(Qp[(size_t)(g + 8) * HD_ + c0 + 4] * 0.125f);
    }

    float o[8][4];
#pragma unroll
    for (int j = 0; j < 8; j++)
#pragma unroll
        for (int e = 0; e < 4; e++) o[j][e] = 0.0f;
    float m_lo = -1e30f, m_hi = -1e30f;
    float l_lo = 0.0f,   l_hi = 0.0f;

    const unsigned FULL = 0xffffffffu;
    const int src0 = (lane & ~3) | (tig >> 1);
    const int src1 = src0 + 2;

    for (int kt = 0; kt < S_ / AKV; kt++) {
        // ---- Fill K,V tiles (global -> smem, tf32-converted) ----
        const float* Kp = Kb + ((size_t)bh * S_ + kt * AKV) * HD_;
        const float* Vp = Vb + ((size_t)bh * S_ + kt * AKV) * HD_;
#pragma unroll
        for (int i = 0; i < 8; i++) {
            int idx = i * 128 + tid;
            int r = idx >> 4;
            int c = (idx & 15) * 4;
            float4 kv = *(const float4*)(Kp + (size_t)r * HD_ + c);
            uint4 kt4 = { f2tf(kv.x), f2tf(kv.y), f2tf(kv.z), f2tf(kv.w) };
            *(uint4*)(Ks + r * AST + c) = kt4;
            float4 vv = *(const float4*)(Vp + (size_t)r * HD_ + c);
            uint4 vt4 = { f2tf(vv.x), f2tf(vv.y), f2tf(vv.z), f2tf(vv.w) };
            *(uint4*)(Vs + r * AST + c) = vt4;
        }
        __syncthreads();

        // ---- S = (scale*Q) @ K^T : 8 n-chunks, accumulators in regs ----
        float s[8][4];
#pragma unroll
        for (int j = 0; j < 8; j++)
#pragma unroll
            for (int e = 0; e < 4; e++) s[j][e] = 0.0f;

#pragma unroll
        for (int kc = 0; kc < 8; kc++) {
            int c0 = kc * 8 + tig;
#pragma unroll
            for (int j = 0; j < 8; j++) {
                unsigned b0 = __float_as_uint(Ks[(j * 8 + g) * AST + c0]);
                unsigned b1 = __float_as_uint(Ks[(j * 8 + g) * AST + c0 + 4]);
                mma_tf32(s[j], qa[kc], b0, b1);
            }
        }

        // ---- Online softmax in registers ----
        float mx_lo = -1e30f, mx_hi = -1e30f;
#pragma unroll
        for (int j = 0; j < 8; j++) {
            mx_lo = fmaxf(mx_lo, fmaxf(s[j][0], s[j][1]));
            mx_hi = fmaxf(mx_hi, fmaxf(s[j][2], s[j][3]));
        }
        mx_lo = fmaxf(mx_lo, __shfl_xor_sync(FULL, mx_lo, 1));
        mx_lo = fmaxf(mx_lo, __shfl_xor_sync(FULL, mx_lo, 2));
        mx_hi = fmaxf(mx_hi, __shfl_xor_sync(FULL, mx_hi, 1));
        mx_hi = fmaxf(mx_hi, __shfl_xor_sync(FULL, mx_hi, 2));

        float mn_lo = fmaxf(m_lo, mx_lo);
        float mn_hi = fmaxf(m_hi, mx_hi);
        float al_lo = __expf(m_lo - mn_lo);
        float al_hi = __expf(m_hi - mn_hi);
        m_lo = mn_lo; m_hi = mn_hi;

        float sum_lo = 0.0f, sum_hi = 0.0f;
#pragma unroll
        for (int j = 0; j < 8; j++) {
            float p0 = __expf(s[j][0] - mn_lo);
            float p1 = __expf(s[j][1] - mn_lo);
            float p2 = __expf(s[j][2] - mn_hi);
            float p3 = __expf(s[j][3] - mn_hi);
            sum_lo += p0 + p1;
            sum_hi += p2 + p3;
            s[j][0] = __uint_as_float(f2tf(p0));
            s[j][1] = __uint_as_float(f2tf(p1));
            s[j][2] = __uint_as_float(f2tf(p2));
            s[j][3] = __uint_as_float(f2tf(p3));
        }
        sum_lo += __shfl_xor_sync(FULL, sum_lo, 1);
        sum_lo += __shfl_xor_sync(FULL, sum_lo, 2);
        sum_hi += __shfl_xor_sync(FULL, sum_hi, 1);
        sum_hi += __shfl_xor_sync(FULL, sum_hi, 2);
        l_lo = l_lo * al_lo + sum_lo;
        l_hi = l_hi * al_hi + sum_hi;

#pragma unroll
        for (int j = 0; j < 8; j++) {
            o[j][0] *= al_lo; o[j][1] *= al_lo;
            o[j][2] *= al_hi; o[j][3] *= al_hi;
        }

        // ---- O += P @ V : build A-frag per k-chunk via lane shuffles ----
#pragma unroll
        for (int kc = 0; kc < 8; kc++) {
            float v00 = __shfl_sync(FULL, s[kc][0], src0);
            float v01 = __shfl_sync(FULL, s[kc][1], src0);
            float v20 = __shfl_sync(FULL, s[kc][2], src0);
            float v21 = __shfl_sync(FULL, s[kc][3], src0);
            float w00 = __shfl_sync(FULL, s[kc][0], src1);
            float w01 = __shfl_sync(FULL, s[kc][1], src1);
            float w20 = __shfl_sync(FULL, s[kc][2], src1);
            float w21 = __shfl_sync(FULL, s[kc][3], src1);
            unsigned pa[4];
            pa[0] = __float_as_uint((tig & 1) ? v01 : v00);  // P[g   ][kc8+tig]
            pa[1] = __float_as_uint((tig & 1) ? v21 : v20);  // P[g+8 ][kc8+tig]
            pa[2] = __float_as_uint((tig & 1) ? w01 : w00);  // P[g   ][kc8+tig+4]
            pa[3] = __float_as_uint((tig & 1) ? w21 : w20);  // P[g+8 ][kc8+tig+4]

            int r0 = (kc * 8 + tig) * AST;
            int r1 = (kc * 8 + tig + 4) * AST;
#pragma unroll
            for (int jn = 0; jn < 8; jn++) {
                unsigned b0 = __float_as_uint(Vs[r0 + jn * 8 + g]);
                unsigned b1 = __float_as_uint(Vs[r1 + jn * 8 + g]);
                mma_tf32(o[jn], pa, b0, b1);
            }
        }
        __syncthreads();
    }

    // ---- Normalize, write to [B,S,D] (merge heads back) ----
    float inv_lo = 1.0f / l_lo;
    float inv_hi = 1.0f / l_hi;
    int b = bh / H_, h = bh % H_;
    float* orow_lo = Ob + ((size_t)(b * S_ + qrow0 + g)) * D_ + h * HD_;
    float* orow_hi = Ob + ((size_t)(b * S_ + qrow0 + g + 8)) * D_ + h * HD_;
#pragma unroll
    for (int jn = 0; jn < 8; jn++) {
        float2 wlo = { o[jn][0] * inv_lo, o[jn][1] * inv_lo };
        float2 whi = { o[jn][2] * inv_hi, o[jn][3] * inv_hi };
        *(float2*)(orow_lo + jn * 8 + 2 * tig) = wlo;
        *(float2*)(orow_hi + jn * 8 + 2 * tig) = whi;
    }
}

// ---------------------------------------------------------------------------
// Launch
// ---------------------------------------------------------------------------
extern "C" void kernel_launch(void* const* d_in, const int* in_sizes, int n_in,
                              void* d_out, int out_size)
{
    (void)in_sizes; (void)n_in; (void)out_size;
    const float* x  = (const float*)d_in[0];
    const float* Wq = (const float*)d_in[1];
    const float* bq = (const float*)d_in[2];
    const float* Wk = (const float*)d_in[3];
    const float* bk = (const float*)d_in[4];
    const float* Wv = (const float*)d_in[5];
    const float* bv = (const float*)d_in[6];
    const float* Wo = (const float*)d_in[7];
    const float* bo = (const float*)d_in[8];
    float* out = (float*)d_out;

    void *pq, *pk, *pv, *patt;
    cudaGetSymbolAddress(&pq, g_q);
    cudaGetSymbolAddress(&pk, g_k);
    cudaGetSymbolAddress(&pv, g_v);
    cudaGetSymbolAddress(&patt, g_att);
    float* qb = (float*)pq;
    float* kb = (float*)pk;
    float* vb = (float*)pv;
    float* ab = (float*)patt;

    dim3 ggrid(D_ / BN, M_TOT / BM);   // (16, 32)
    gemm_tf32_kernel<<<ggrid, 256>>>(x, Wq, bq, qb, M_TOT, D_, D_, 1);
    gemm_tf32_kernel<<<ggrid, 256>>>(x, Wk, bk, kb, M_TOT, D_, D_, 1);
    gemm_tf32_kernel<<<ggrid, 256>>>(x, Wv, bv, vb, M_TOT, D_, D_, 1);

    dim3 agrid(S_ / AQ, B_ * H_);      // (32, 32)
    attn_kernel<<<agrid, 128>>>(qb, kb, vb, ab);

    gemm_tf32_kernel<<<ggrid, 256>>>(ab, Wo, bo, out, M_TOT, D_, D_, 0);
}

// round 3
// speedup vs baseline: 1.8496x; 1.2379x over previous
#include <cuda_runtime.h>

// Problem constants (fixed shapes)
#define B_   2
#define S_   2048
#define D_   1024
#define H_   16
#define HD_  64
#define M_TOT (B_ * S_)   // 4096

// ---------------------------------------------------------------------------
// Scratch buffers
// ---------------------------------------------------------------------------
__device__ float g_q[B_ * H_ * S_ * HD_];    // [B,H,S,HD]
__device__ float g_k[B_ * H_ * S_ * HD_];
__device__ float g_v[B_ * H_ * S_ * HD_];
__device__ float g_att[B_ * S_ * D_];        // [B,S,D]

// ---------------------------------------------------------------------------
// Helpers
// ---------------------------------------------------------------------------
__device__ __forceinline__ unsigned f2tf(float x) {
    unsigned u;
    asm("cvt.rna.tf32.f32 %0, %1;" : "=r"(u) : "f"(x));
    return u;
}

__device__ __forceinline__ void mma_tf32(float* d, const unsigned* a,
                                         unsigned b0, unsigned b1) {
    asm volatile(
        "mma.sync.aligned.m16n8k8.row.col.f32.tf32.tf32.f32 "
        "{%0,%1,%2,%3}, {%4,%5,%6,%7}, {%8,%9}, {%0,%1,%2,%3};"
        : "+f"(d[0]), "+f"(d[1]), "+f"(d[2]), "+f"(d[3])
        : "r"(a[0]), "r"(a[1]), "r"(a[2]), "r"(a[3]), "r"(b0), "r"(b1));
}

// ---------------------------------------------------------------------------
// Pipelined TF32 GEMM: out = A[M,K] @ W[K,N] + bias
// CTA tile 128x128x32, 8 warps (2x4), warp tile 64x32 (4x4 m16n8k8 frags).
// Register-prefetch software pipeline; register epilogue with optional
// [B,H,S,HD] scatter for QKV.
// ---------------------------------------------------------------------------
#define GBM 128
#define GBN 128
#define GBK 32
#define GASTR 36    // (4g+tig)%32 all-distinct for frag loads
#define GBSTR 136   // (8tig+g)%32 all-distinct for frag loads

__global__ void __launch_bounds__(256, 2) gemm_tf32_kernel(
    const float* __restrict__ A, const float* __restrict__ W,
    const float* __restrict__ bias, float* __restrict__ out,
    int M, int N, int K, int qkv_mode)
{
    __shared__ float As[GBM * GASTR];   // 18 KB
    __shared__ float Bs[GBK * GBSTR];   // 17 KB

    const int tid  = threadIdx.x;
    const int warp = tid >> 5;
    const int lane = tid & 31;
    const int g    = lane >> 2;
    const int tig  = lane & 3;
    const int wm   = (warp >> 2) * 64;      // 0, 64
    const int wn   = (warp & 3) * 32;       // 0, 32, 64, 96
    const int bm   = blockIdx.y * GBM;
    const int bn   = blockIdx.x * GBN;

    // Global-load thread mappings
    const int arow = tid >> 1;              // 0..127
    const int acol = (tid & 1) * 16;        // 0, 16
    const int brow = tid >> 3;              // 0..31
    const int bcol = (tid & 7) * 16;        // 0..112

    float acc[16][4];
#pragma unroll
    for (int f = 0; f < 16; f++)
#pragma unroll
        for (int e = 0; e < 4; e++) acc[f][e] = 0.0f;

    const float* Aro = A + (size_t)(bm + arow) * K + acol;
    const float* Bro = W + (size_t)brow * N + bn + bcol;

    float4 ra[4], rb[4];

    // ---- Prologue: tile 0 -> regs -> smem ----
#pragma unroll
    for (int p = 0; p < 4; p++) ra[p] = *(const float4*)(Aro + p * 4);
#pragma unroll
    for (int p = 0; p < 4; p++) rb[p] = *(const float4*)(Bro + p * 4);
#pragma unroll
    for (int p = 0; p < 4; p++) {
        uint4 t = { f2tf(ra[p].x), f2tf(ra[p].y), f2tf(ra[p].z), f2tf(ra[p].w) };
        *(uint4*)(As + arow * GASTR + acol + p * 4) = t;
        uint4 u = { f2tf(rb[p].x), f2tf(rb[p].y), f2tf(rb[p].z), f2tf(rb[p].w) };
        *(uint4*)(Bs + brow * GBSTR + bcol + p * 4) = u;
    }
    __syncthreads();

    const int NT = K / GBK;
    for (int t = 0; t < NT; t++) {
        // Prefetch next tile into registers (latency hides under MMAs)
        if (t + 1 < NT) {
            const float* An = Aro + (t + 1) * GBK;
            const float* Bn = Bro + (size_t)(t + 1) * GBK * N;
#pragma unroll
            for (int p = 0; p < 4; p++) ra[p] = *(const float4*)(An + p * 4);
#pragma unroll
            for (int p = 0; p < 4; p++) rb[p] = *(const float4*)(Bn + p * 4);
        }

        // Compute on current smem tile
#pragma unroll
        for (int kk = 0; kk < GBK; kk += 8) {
            unsigned af[4][4];
#pragma unroll
            for (int i = 0; i < 4; i++) {
                const float* base = As + (wm + i * 16 + g) * GASTR + kk + tig;
                af[i][0] = __float_as_uint(base[0]);
                af[i][1] = __float_as_uint(base[8 * GASTR]);
                af[i][2] = __float_as_uint(base[4]);
                af[i][3] = __float_as_uint(base[8 * GASTR + 4]);
            }
            unsigned bf[4][2];
#pragma unroll
            for (int j = 0; j < 4; j++) {
                bf[j][0] = __float_as_uint(Bs[(kk + tig) * GBSTR + wn + j * 8 + g]);
                bf[j][1] = __float_as_uint(Bs[(kk + tig + 4) * GBSTR + wn + j * 8 + g]);
            }
#pragma unroll
            for (int i = 0; i < 4; i++)
#pragma unroll
                for (int j = 0; j < 4; j++)
                    mma_tf32(acc[i * 4 + j], af[i], bf[j][0], bf[j][1]);
        }
        __syncthreads();

        if (t + 1 < NT) {
#pragma unroll
            for (int p = 0; p < 4; p++) {
                uint4 ta = { f2tf(ra[p].x), f2tf(ra[p].y), f2tf(ra[p].z), f2tf(ra[p].w) };
                *(uint4*)(As + arow * GASTR + acol + p * 4) = ta;
                uint4 tb = { f2tf(rb[p].x), f2tf(rb[p].y), f2tf(rb[p].z), f2tf(rb[p].w) };
                *(uint4*)(Bs + brow * GBSTR + bcol + p * 4) = tb;
            }
            __syncthreads();
        }
    }

    // ---- Register epilogue: bias + direct store (optional head scatter) ----
#pragma unroll
    for (int i = 0; i < 4; i++) {
#pragma unroll
        for (int j = 0; j < 4; j++) {
            const float* d = acc[i * 4 + j];
            int col = bn + wn + j * 8 + 2 * tig;
            float2 b2 = *(const float2*)(bias + col);
            int row_lo = bm + wm + i * 16 + g;
            float2 vlo = { d[0] + b2.x, d[1] + b2.y };
            float2 vhi = { d[2] + b2.x, d[3] + b2.y };
            if (qkv_mode) {
                int h = col / HD_, dd = col % HD_;
                int b0i = row_lo / S_, s0 = row_lo % S_;
                *(float2*)(out + ((size_t)((b0i * H_ + h) * S_ + s0)) * HD_ + dd) = vlo;
                int row_hi = row_lo + 8;
                int b1i = row_hi / S_, s1 = row_hi % S_;
                *(float2*)(out + ((size_t)((b1i * H_ + h) * S_ + s1)) * HD_ + dd) = vhi;
            } else {
                *(float2*)(out + (size_t)row_lo * N + col) = vlo;
                *(float2*)(out + (size_t)(row_lo + 8) * N + col) = vhi;
            }
        }
    }
}

// ---------------------------------------------------------------------------
// Flash attention (unchanged from R2): register-resident S/P/O, mma.m16n8k8.
// ---------------------------------------------------------------------------
#define AQ  64
#define AKV 64
#define AST 68

__global__ void __launch_bounds__(128) attn_kernel(
    const float* __restrict__ Qb, const float* __restrict__ Kb,
    const float* __restrict__ Vb, float* __restrict__ Ob)
{
    __shared__ float Ks[AKV * AST];
    __shared__ float Vs[AKV * AST];

    const int bh   = blockIdx.y;
    const int qt   = blockIdx.x;
    const int tid  = threadIdx.x;
    const int warp = tid >> 5;
    const int lane = tid & 31;
    const int g    = lane >> 2;
    const int tig  = lane & 3;

    const int qrow0 = qt * AQ + warp * 16;
    const float* Qp = Qb + ((size_t)bh * S_ + qrow0) * HD_;
    unsigned qa[8][4];
#pragma unroll
    for (int kc = 0; kc < 8; kc++) {
        int c0 = kc * 8 + tig;
        qa[kc][0] = f2tf(Qp[(size_t)g * HD_ + c0] * 0.125f);
        qa[kc][1] = f2tf(Qp[(size_t)(g + 8) * HD_ + c0] * 0.125f);
        qa[kc][2] = f2tf(Qp[(size_t)g * HD_ + c0 + 4] * 0.125f);
        qa[kc][3] = f2tf(Qp[(size_t)(g + 8) * HD_ + c0 + 4] * 0.125f);
    }

    float o[8][4];
#pragma unroll
    for (int j = 0; j < 8; j++)
#pragma unroll
        for (int e = 0; e < 4; e++) o[j][e] = 0.0f;
    float m_lo = -1e30f, m_hi = -1e30f;
    float l_lo = 0.0f,   l_hi = 0.0f;

    const unsigned FULL = 0xffffffffu;
    const int src0 = (lane & ~3) | (tig >> 1);
    const int src1 = src0 + 2;

    for (int kt = 0; kt < S_ / AKV; kt++) {
        const float* Kp = Kb + ((size_t)bh * S_ + kt * AKV) * HD_;
        const float* Vp = Vb + ((size_t)bh * S_ + kt * AKV) * HD_;
#pragma unroll
        for (int i = 0; i < 8; i++) {
            int idx = i * 128 + tid;
            int r = idx >> 4;
            int c = (idx & 15) * 4;
            float4 kv = *(const float4*)(Kp + (size_t)r * HD_ + c);
            uint4 kt4 = { f2tf(kv.x), f2tf(kv.y), f2tf(kv.z), f2tf(kv.w) };
            *(uint4*)(Ks + r * AST + c) = kt4;
            float4 vv = *(const float4*)(Vp + (size_t)r * HD_ + c);
            uint4 vt4 = { f2tf(vv.x), f2tf(vv.y), f2tf(vv.z), f2tf(vv.w) };
            *(uint4*)(Vs + r * AST + c) = vt4;
        }
        __syncthreads();

        float s[8][4];
#pragma unroll
        for (int j = 0; j < 8; j++)
#pragma unroll
            for (int e = 0; e < 4; e++) s[j][e] = 0.0f;

#pragma unroll
        for (int kc = 0; kc < 8; kc++) {
            int c0 = kc * 8 + tig;
#pragma unroll
            for (int j = 0; j < 8; j++) {
                unsigned b0 = __float_as_uint(Ks[(j * 8 + g) * AST + c0]);
                unsigned b1 = __float_as_uint(Ks[(j * 8 + g) * AST + c0 + 4]);
                mma_tf32(s[j], qa[kc], b0, b1);
            }
        }

        float mx_lo = -1e30f, mx_hi = -1e30f;
#pragma unroll
        for (int j = 0; j < 8; j++) {
            mx_lo = fmaxf(mx_lo, fmaxf(s[j][0], s[j][1]));
            mx_hi = fmaxf(mx_hi, fmaxf(s[j][2], s[j][3]));
        }
        mx_lo = fmaxf(mx_lo, __shfl_xor_sync(FULL, mx_lo, 1));
        mx_lo = fmaxf(mx_lo, __shfl_xor_sync(FULL, mx_lo, 2));
        mx_hi = fmaxf(mx_hi, __shfl_xor_sync(FULL, mx_hi, 1));
        mx_hi = fmaxf(mx_hi, __shfl_xor_sync(FULL, mx_hi, 2));

        float mn_lo = fmaxf(m_lo, mx_lo);
        float mn_hi = fmaxf(m_hi, mx_hi);
        float al_lo = __expf(m_lo - mn_lo);
        float al_hi = __expf(m_hi - mn_hi);
        m_lo = mn_lo; m_hi = mn_hi;

        float sum_lo = 0.0f, sum_hi = 0.0f;
#pragma unroll
        for (int j = 0; j < 8; j++) {
            float p0 = __expf(s[j][0] - mn_lo);
            float p1 = __expf(s[j][1] - mn_lo);
            float p2 = __expf(s[j][2] - mn_hi);
            float p3 = __expf(s[j][3] - mn_hi);
            sum_lo += p0 + p1;
            sum_hi += p2 + p3;
            s[j][0] = __uint_as_float(f2tf(p0));
            s[j][1] = __uint_as_float(f2tf(p1));
            s[j][2] = __uint_as_float(f2tf(p2));
            s[j][3] = __uint_as_float(f2tf(p3));
        }
        sum_lo += __shfl_xor_sync(FULL, sum_lo, 1);
        sum_lo += __shfl_xor_sync(FULL, sum_lo, 2);
        sum_hi += __shfl_xor_sync(FULL, sum_hi, 1);
        sum_hi += __shfl_xor_sync(FULL, sum_hi, 2);
        l_lo = l_lo * al_lo + sum_lo;
        l_hi = l_hi * al_hi + sum_hi;

#pragma unroll
        for (int j = 0; j < 8; j++) {
            o[j][0] *= al_lo; o[j][1] *= al_lo;
            o[j][2] *= al_hi; o[j][3] *= al_hi;
        }

#pragma unroll
        for (int kc = 0; kc < 8; kc++) {
            float v00 = __shfl_sync(FULL, s[kc][0], src0);
            float v01 = __shfl_sync(FULL, s[kc][1], src0);
            float v20 = __shfl_sync(FULL, s[kc][2], src0);
            float v21 = __shfl_sync(FULL, s[kc][3], src0);
            float w00 = __shfl_sync(FULL, s[kc][0], src1);
            float w01 = __shfl_sync(FULL, s[kc][1], src1);
            float w20 = __shfl_sync(FULL, s[kc][2], src1);
            float w21 = __shfl_sync(FULL, s[kc][3], src1);
            unsigned pa[4];
            pa[0] = __float_as_uint((tig & 1) ? v01 : v00);
            pa[1] = __float_as_uint((tig & 1) ? v21 : v20);
            pa[2] = __float_as_uint((tig & 1) ? w01 : w00);
            pa[3] = __float_as_uint((tig & 1) ? w21 : w20);

            int r0 = (kc * 8 + tig) * AST;
            int r1 = (kc * 8 + tig + 4) * AST;
#pragma unroll
            for (int jn = 0; jn < 8; jn++) {
                unsigned b0 = __float_as_uint(Vs[r0 + jn * 8 + g]);
                unsigned b1 = __float_as_uint(Vs[r1 + jn * 8 + g]);
                mma_tf32(o[jn], pa, b0, b1);
            }
        }
        __syncthreads();
    }

    float inv_lo = 1.0f / l_lo;
    float inv_hi = 1.0f / l_hi;
    int b = bh / H_, h = bh % H_;
    float* orow_lo = Ob + ((size_t)(b * S_ + qrow0 + g)) * D_ + h * HD_;
    float* orow_hi = Ob + ((size_t)(b * S_ + qrow0 + g + 8)) * D_ + h * HD_;
#pragma unroll
    for (int jn = 0; jn < 8; jn++) {
        float2 wlo = { o[jn][0] * inv_lo, o[jn][1] * inv_lo };
        float2 whi = { o[jn][2] * inv_hi, o[jn][3] * inv_hi };
        *(float2*)(orow_lo + jn * 8 + 2 * tig) = wlo;
        *(float2*)(orow_hi + jn * 8 + 2 * tig) = whi;
    }
}

// ---------------------------------------------------------------------------
// Launch
// ---------------------------------------------------------------------------
extern "C" void kernel_launch(void* const* d_in, const int* in_sizes, int n_in,
                              void* d_out, int out_size)
{
    (void)in_sizes; (void)n_in; (void)out_size;
    const float* x  = (const float*)d_in[0];
    const float* Wq = (const float*)d_in[1];
    const float* bq = (const float*)d_in[2];
    const float* Wk = (const float*)d_in[3];
    const float* bk = (const float*)d_in[4];
    const float* Wv = (const float*)d_in[5];
    const float* bv = (const float*)d_in[6];
    const float* Wo = (const float*)d_in[7];
    const float* bo = (const float*)d_in[8];
    float* out = (float*)d_out;

    void *pq, *pk, *pv, *patt;
    cudaGetSymbolAddress(&pq, g_q);
    cudaGetSymbolAddress(&pk, g_k);
    cudaGetSymbolAddress(&pv, g_v);
    cudaGetSymbolAddress(&patt, g_att);
    float* qb = (float*)pq;
    float* kb = (float*)pk;
    float* vb = (float*)pv;
    float* ab = (float*)patt;

    dim3 ggrid(D_ / GBN, M_TOT / GBM);   // (8, 32)
    gemm_tf32_kernel<<<ggrid, 256>>>(x, Wq, bq, qb, M_TOT, D_, D_, 1);
    gemm_tf32_kernel<<<ggrid, 256>>>(x, Wk, bk, kb, M_TOT, D_, D_, 1);
    gemm_tf32_kernel<<<ggrid, 256>>>(x, Wv, bv, vb, M_TOT, D_, D_, 1);

    dim3 agrid(S_ / AQ, B_ * H_);        // (32, 32)
    attn_kernel<<<agrid, 128>>>(qb, kb, vb, ab);

    gemm_tf32_kernel<<<ggrid, 256>>>(ab, Wo, bo, out, M_TOT, D_, D_, 0);
}